// round 14
// baseline (speedup 1.0000x reference)
#include <cuda_runtime.h>
#include <cuda_bf16.h>
#include <math.h>

// Problem shapes (fixed dataset): N=F=16384, G=8192, S=16
#define MAXN    16384
#define MAXF    16384
#define MAXG    8192
#define SMP     16
#define MAXQR   (MAXG * SMP)        // 131072 reverse queries
#define MAXT    (MAXN + MAXF + MAXQR + MAXG)   // 172032 items total

// Uniform grid over [-4.75, 4.75]^3; out-of-range points clamp into edge
// cells (conservative for the shell termination bound).
#define GD      48
#define CELLS   (GD * GD * GD)      // 110592
#define LOB     (-4.75f)
#define HCELL   (9.5f / (float)GD)
#define CHUNK   1024
#define NCH     (CELLS / CHUNK)     // 108

__device__ int    g_cnt[4][CELLS];
__device__ int    g_starts[4][CELLS + 1];
__device__ int    g_cursor[4][CELLS];
__device__ int    g_chtot[4][NCH];
__device__ float4 g_stage[MAXT];    // staged (x,y,z,prob) from k_count
__device__ float4 g_sref0[MAXN];    // orig vertices  (x,y,z,|p|^2), cell-sorted
__device__ float4 g_sref1[MAXF];    // orig barycenters
__device__ float4 g_sq0[MAXQR];     // reverse queries, cell-sorted
__device__ float  g_sp0[MAXQR];
__device__ float4 g_sq1[MAXG];      // forward queries
__device__ float  g_sp1[MAXG];
__device__ unsigned g_done;
__device__ double g_fwd, g_rev;
__device__ unsigned g_maxbits;

__device__ __forceinline__ int cellof(float x) {
    int c = (int)floorf((x - LOB) * (1.0f / HCELL));
    return min(max(c, 0), GD - 1);
}

// Deterministic item generator (count pass only; fill reads the stage).
__device__ __forceinline__ void item(
    int idx,
    const float* __restrict__ ov, const int* __restrict__ of,
    const float* __restrict__ sv, const int* __restrict__ sf,
    const float* __restrict__ probs,
    const float* __restrict__ r1, const float* __restrict__ r2,
    int N, int F, int G, int S,
    float& x, float& y, float& z, float& prob)
{
    if (idx < N) {
        prob = 0.f;
        x = ov[3*idx]; y = ov[3*idx+1]; z = ov[3*idx+2];
    } else if (idx < N + F) {
        prob = 0.f;
        int f = idx - N;
        int i0 = of[3*f], i1 = of[3*f+1], i2 = of[3*f+2];
        x = (ov[3*i0  ] + ov[3*i1  ] + ov[3*i2  ]) * (1.f/3.f);
        y = (ov[3*i0+1] + ov[3*i1+1] + ov[3*i2+1]) * (1.f/3.f);
        z = (ov[3*i0+2] + ov[3*i1+2] + ov[3*i2+2]) * (1.f/3.f);
    } else if (idx < N + F + G * S) {
        int q = idx - N - F;
        int g = q / S;
        int i0 = sf[3*g], i1 = sf[3*g+1], i2 = sf[3*g+2];
        float sq = sqrtf(r1[q]);
        float rr2 = r2[q];
        float u = 1.f - sq, v = sq * (1.f - rr2), w = sq * rr2;
        x = u*sv[3*i0  ] + v*sv[3*i1  ] + w*sv[3*i2  ];
        y = u*sv[3*i0+1] + v*sv[3*i1+1] + w*sv[3*i2+1];
        z = u*sv[3*i0+2] + v*sv[3*i1+2] + w*sv[3*i2+2];
        prob = probs[g];
    } else {
        int g = idx - N - F - G * S;
        int i0 = sf[3*g], i1 = sf[3*g+1], i2 = sf[3*g+2];
        x = (sv[3*i0  ] + sv[3*i1  ] + sv[3*i2  ]) * (1.f/3.f);
        y = (sv[3*i0+1] + sv[3*i1+1] + sv[3*i2+1]) * (1.f/3.f);
        z = (sv[3*i0+2] + sv[3*i1+2] + sv[3*i2+2]) * (1.f/3.f);
        prob = probs[g];
    }
}

// ---------------------------------------------------------------------------
__global__ void k_zero()
{
    int idx = blockIdx.x * blockDim.x + threadIdx.x;
    if (idx == 0) { g_fwd = 0.0; g_rev = 0.0; g_maxbits = 0u; g_done = 0u; }
    if (idx < 4 * CELLS) ((int*)g_cnt)[idx] = 0;
}

__global__ void k_count(const float* __restrict__ ov, const int* __restrict__ of,
                        const float* __restrict__ sv, const int* __restrict__ sf,
                        const float* __restrict__ probs,
                        const float* __restrict__ r1, const float* __restrict__ r2,
                        int N, int F, int G, int S, int T)
{
    int idx = blockIdx.x * blockDim.x + threadIdx.x;
    if (idx >= T) return;
    float x, y, z, p;
    item(idx, ov, of, sv, sf, probs, r1, r2, N, F, G, S, x, y, z, p);
    g_stage[idx] = make_float4(x, y, z, p);
    const int set = (idx < N) ? 0 : (idx < N + F) ? 1 : (idx < N + F + G*S) ? 2 : 3;
    int cid = (cellof(z) * GD + cellof(y)) * GD + cellof(x);
    atomicAdd(&g_cnt[set][cid], 1);
}

// Per-chunk exclusive scan via shfl (2 barriers), chunk totals out.
__global__ void k_scanA()
{
    const int a = blockIdx.x / NCH, j = blockIdx.x % NCH;
    const int t = threadIdx.x;
    const int wid = t >> 5, lane = t & 31;
    __shared__ int wsum[32];

    int v = g_cnt[a][j * CHUNK + t];
    int inc = v;
    #pragma unroll
    for (int o = 1; o < 32; o <<= 1) {
        int u = __shfl_up_sync(0xFFFFFFFFu, inc, o);
        if (lane >= o) inc += u;
    }
    if (lane == 31) wsum[wid] = inc;
    __syncthreads();
    if (wid == 0) {
        int w = wsum[lane];
        #pragma unroll
        for (int o = 1; o < 32; o <<= 1) {
            int u = __shfl_up_sync(0xFFFFFFFFu, w, o);
            if (lane >= o) w += u;
        }
        wsum[lane] = w;
    }
    __syncthreads();
    const int inclusive = inc + (wid ? wsum[wid - 1] : 0);
    g_starts[a][j * CHUNK + t] = inclusive - v;
    if (t == CHUNK - 1) g_chtot[a][j] = inclusive;
}

// Each chunk block computes its global offset (warp-reduce over preceding
// chunk totals) and applies it; writes starts + cursor + sentinel.
__global__ void k_scanBC()
{
    const int a = blockIdx.x / NCH, j = blockIdx.x % NCH;
    const int t = threadIdx.x;
    __shared__ int s_off;
    if (t < 32) {
        int acc = 0;
        for (int i = t; i < j; i += 32) acc += g_chtot[a][i];
        #pragma unroll
        for (int o = 16; o > 0; o >>= 1)
            acc += __shfl_xor_sync(0xFFFFFFFFu, acc, o);
        if (t == 0) s_off = acc;
    }
    __syncthreads();
    const int off = s_off;
    const int idx = j * CHUNK + t;
    int s = g_starts[a][idx] + off;
    g_starts[a][idx] = s;
    g_cursor[a][idx] = s;
    if (j == NCH - 1 && t == CHUNK - 1)
        g_starts[a][CELLS] = s + g_cnt[a][idx];
}

// Fill from the staged points (coalesced read; no regathering).
__global__ void k_fill(int N, int F, int G, int S, int T)
{
    int idx = blockIdx.x * blockDim.x + threadIdx.x;
    if (idx >= T) return;
    float4 st4 = g_stage[idx];
    const float x = st4.x, y = st4.y, z = st4.z, p = st4.w;
    const int set = (idx < N) ? 0 : (idx < N + F) ? 1 : (idx < N + F + G*S) ? 2 : 3;
    int cid = (cellof(z) * GD + cellof(y)) * GD + cellof(x);
    int pos = atomicAdd(&g_cursor[set][cid], 1);
    float4 v4 = make_float4(x, y, z, x*x + y*y + z*z);
    if      (set == 0) g_sref0[pos] = v4;
    else if (set == 1) g_sref1[pos] = v4;
    else if (set == 2) { g_sq0[pos] = v4; g_sp0[pos] = p; }
    else               { g_sq1[pos] = v4; g_sp1[pos] = p; }
}

// ---------------------------------------------------------------------------
// Warp-cooperative shell walk from r=2 with seeded best (exact; identical
// candidate enumeration to the former k_query2). Returns warp-min best.
// All 32 lanes participate; per-shell termination test is warp-uniform.
// ---------------------------------------------------------------------------
__device__ float coop_shell(float qx, float qy, float qz, float qq, float best,
                            const float4* __restrict__ refs,
                            const int* __restrict__ st, int lane)
{
    const float a = -2.f * qx, b = -2.f * qy, c = -2.f * qz;
    const int cx = cellof(qx), cy = cellof(qy), cz = cellof(qz);

    for (int r = 2; r < GD; r++) {
        const int xlo = max(cx - r, 0), xhi = min(cx + r, GD - 1);
        const int ylo = max(cy - r, 0), yhi = min(cy + r, GD - 1);
        const int zlo = max(cz - r, 0), zhi = min(cz + r, GD - 1);
        const unsigned ny   = (unsigned)(yhi - ylo + 1);
        const int      xlen = xhi - xlo + 1;

        int capcnt = 0, capz0 = 0, capz1 = 0;
        if (cz - r >= 0)      { capz0 = cz - r; capcnt = 1; }
        if (cz + r <= GD - 1) { if (capcnt == 0) capz0 = cz + r; else capz1 = cz + r; capcnt++; }
        const int izlo = max(cz - r + 1, 0), izhi = min(cz + r - 1, GD - 1);
        const unsigned nzint = (unsigned)max(izhi - izlo + 1, 0);
        int nys = 0, ys0 = 0, ys1 = 0;
        if (cy - r >= 0)      { ys0 = cy - r; nys = 1; }
        if (cy + r <= GD - 1) { if (nys == 0) ys0 = cy + r; else ys1 = cy + r; nys++; }
        const int iylo = max(cy - r + 1, 0), iyhi = min(cy + r - 1, GD - 1);
        const unsigned nyint = (unsigned)max(iyhi - iylo + 1, 0);
        int nxs = 0, xs0 = 0, xs1 = 0;
        if (cx - r >= 0)      { xs0 = cx - r; nxs = 1; }
        if (cx + r <= GD - 1) { if (nxs == 0) xs0 = cx + r; else xs1 = cx + r; nxs++; }

        const unsigned nA = (unsigned)capcnt * ny;
        const unsigned nB = (unsigned)nys * nzint;
        const unsigned nzy = nzint * nyint;
        const unsigned nC = (unsigned)nxs * nzy;
        const unsigned tot = nA + nB + nC;

        for (unsigned t = (unsigned)lane; t < tot; t += 32) {
            int c0, len;
            if (t < nA) {
                unsigned ci = t / ny, yr = t - ci * ny;
                int z = ci ? capz1 : capz0;
                c0 = (z * GD + (ylo + (int)yr)) * GD + xlo; len = xlen;
            } else if (t < nA + nB) {
                unsigned t2 = t - nA;
                unsigned si = t2 / nzint, zi = t2 - si * nzint;
                int y = si ? ys1 : ys0;
                c0 = (((int)zi + izlo) * GD + y) * GD + xlo; len = xlen;
            } else {
                unsigned t3 = t - nA - nB;
                unsigned xi = t3 / nzy, rem = t3 - xi * nzy;
                unsigned zi = rem / nyint, yi = rem - zi * nyint;
                int x = xi ? xs1 : xs0;
                c0 = (((int)zi + izlo) * GD + ((int)yi + iylo)) * GD + x; len = 1;
            }
            const int s = st[c0], e = st[c0 + len];
            for (int i = s; i < e; i++) {
                float4 wv = refs[i];
                best = fminf(best, fmaf(a, wv.x, fmaf(b, wv.y, fmaf(c, wv.z, wv.w))));
            }
        }

        #pragma unroll
        for (int o = 16; o > 0; o >>= 1)
            best = fminf(best, __shfl_xor_sync(0xFFFFFFFFu, best, o));

        const float d2 = fmaxf(best + qq, 0.f);
        const float cov = (float)r * HCELL;
        if (d2 <= cov * cov) break;
        if (xlo == 0 && ylo == 0 && zlo == 0 &&
            xhi == GD - 1 && yhi == GD - 1 && zhi == GD - 1) break;
    }
    return best;    // warp-uniform
}

// ---------------------------------------------------------------------------
// Single query kernel: thread-per-query flat 3x3x3 scan over CELL-SORTED
// queries (coherence is load-bearing — R12 measured +30us without it);
// certify with d <= h (sound). Uncertified lanes handled immediately by the
// whole warp via ballot + cooperative shell walk. Last block finalizes.
// ---------------------------------------------------------------------------
#define QT 256
#define NQB ((MAXQR + QT - 1) / QT + (MAXG + QT - 1) / QT)
__global__ void __launch_bounds__(QT)
k_query(int brev, int nq_rev, int nq_fwd, int nblocks, float* __restrict__ out)
{
    const bool rev = (blockIdx.x < (unsigned)brev);
    const float4* __restrict__ refs = rev ? g_sref0     : g_sref1;
    const int*    __restrict__ st   = rev ? g_starts[0] : g_starts[1];
    const float4* __restrict__ qarr = rev ? g_sq0       : g_sq1;
    const float*  __restrict__ parr = rev ? g_sp0       : g_sp1;
    const int nq = rev ? nq_rev : nq_fwd;
    const int qi = (rev ? blockIdx.x : blockIdx.x - brev) * QT + threadIdx.x;
    const int lane = threadIdx.x & 31;

    const bool valid = (qi < nq);
    float4 Q = valid ? qarr[qi] : make_float4(0.f, 0.f, 0.f, 0.f);
    const float qq = Q.w;
    float best = 3.4e38f;

    if (valid) {
        const float a = -2.f * Q.x, b = -2.f * Q.y, c = -2.f * Q.z;
        const int cx = cellof(Q.x), cy = cellof(Q.y), cz = cellof(Q.z);
        const int xlo = max(cx - 1, 0), xhi = min(cx + 1, GD - 1);
        const int xn  = xhi - xlo + 1;

        int s[9], e[9];
        #pragma unroll
        for (int dz = 0; dz < 3; dz++) {
            #pragma unroll
            for (int dy = 0; dy < 3; dy++) {
                const int z = cz + dz - 1, y = cy + dy - 1;
                const int k = dz * 3 + dy;
                if (z < 0 || z >= GD || y < 0 || y >= GD) { s[k] = 0; e[k] = 0; }
                else {
                    const int c0 = (z * GD + y) * GD + xlo;
                    s[k] = st[c0]; e[k] = st[c0 + xn];
                }
            }
        }

        #pragma unroll
        for (int k = 0; k < 9; k++) {
            for (int i = s[k]; i < e[k]; i++) {
                float4 w = refs[i];
                best = fminf(best, fmaf(a, w.x, fmaf(b, w.y, fmaf(c, w.z, w.w))));
            }
        }
    }

    // Certification: after the full 3^3 box, any unscanned point is >= h away.
    const float d2flat = fmaxf(best + qq, 0.f);
    const bool cert = !valid || (d2flat <= HCELL * HCELL);

    // Warp-cooperative handling of uncertified lanes (~12%).
    unsigned pend = __ballot_sync(0xFFFFFFFFu, !cert);
    while (pend) {
        const int src = __ffs(pend) - 1;
        pend &= pend - 1;
        const float bqx = __shfl_sync(0xFFFFFFFFu, Q.x, src);
        const float bqy = __shfl_sync(0xFFFFFFFFu, Q.y, src);
        const float bqz = __shfl_sync(0xFFFFFFFFu, Q.z, src);
        const float bqq = __shfl_sync(0xFFFFFFFFu, qq,  src);
        const float b0  = __shfl_sync(0xFFFFFFFFu, best, src);
        const float nb = coop_shell(bqx, bqy, bqz, bqq, b0, refs, st, lane);
        if (lane == src) best = nb;
    }

    float contrib = 0.f, dmax = 0.f;
    if (valid) {
        const float d = sqrtf(fmaxf(best + qq, 1e-12f));
        const float p = parr[qi];
        contrib = rev ? p * d : fmaf(p, d, 1e-4f * (1.f - p));
        if (rev) dmax = d;
    }

    float sv2 = contrib, mv = dmax;
    #pragma unroll
    for (int o = 16; o > 0; o >>= 1) {
        sv2 += __shfl_xor_sync(0xFFFFFFFFu, sv2, o);
        mv = fmaxf(mv, __shfl_xor_sync(0xFFFFFFFFu, mv, o));
    }
    __shared__ float rs[QT / 32], rm[QT / 32];
    const int warp = threadIdx.x >> 5;
    if (lane == 0) { rs[warp] = sv2; rm[warp] = mv; }
    __syncthreads();
    if (threadIdx.x == 0) {
        float s2 = 0.f, m2 = 0.f;
        #pragma unroll
        for (int i = 0; i < QT / 32; i++) { s2 += rs[i]; m2 = fmaxf(m2, rm[i]); }
        atomicAdd(rev ? &g_rev : &g_fwd, (double)s2);
        if (rev) atomicMax(&g_maxbits, __float_as_uint(m2));

        __threadfence();
        unsigned ticket = atomicAdd(&g_done, 1u);
        if (ticket == (unsigned)(nblocks - 1)) {
            float maxd = __uint_as_float(g_maxbits) + 1e-8f;
            double result = g_fwd + g_rev * (0.1 / (double)maxd);
            out[0] = (float)result;
        }
    }
}

// ---------------------------------------------------------------------------
extern "C" void kernel_launch(void* const* d_in, const int* in_sizes, int n_in,
                              void* d_out, int out_size)
{
    const float* ov    = (const float*)d_in[0];
    const int*   of    = (const int*)  d_in[1];
    const float* sv    = (const float*)d_in[2];
    const int*   sf    = (const int*)  d_in[3];
    const float* probs = (const float*)d_in[4];
    const float* r1    = (const float*)d_in[5];
    const float* r2    = (const float*)d_in[6];

    const int N = in_sizes[0] / 3;     // 16384
    const int F = in_sizes[1] / 3;     // 16384
    const int G = in_sizes[3] / 3;     // 8192
    const int S = in_sizes[5] / G;     // 16

    const int nq_rev = G * S;          // 131072
    const int nq_fwd = G;              // 8192
    const int T = N + F + nq_rev + nq_fwd;

    k_zero  <<<(4 * CELLS + 255) / 256, 256>>>();
    k_count <<<(T + 255) / 256, 256>>>(ov, of, sv, sf, probs, r1, r2, N, F, G, S, T);
    k_scanA <<<4 * NCH, CHUNK>>>();
    k_scanBC<<<4 * NCH, CHUNK>>>();
    k_fill  <<<(T + 255) / 256, 256>>>(N, F, G, S, T);

    const int brev = (nq_rev + QT - 1) / QT;   // 512
    const int bfwd = (nq_fwd + QT - 1) / QT;   // 32
    k_query<<<brev + bfwd, QT>>>(brev, nq_rev, nq_fwd, brev + bfwd, (float*)d_out);
}

// round 15
// speedup vs baseline: 1.0004x; 1.0004x over previous
#include <cuda_runtime.h>
#include <cuda_bf16.h>
#include <math.h>

// Problem shapes (fixed dataset): N=F=16384, G=8192, S=16
#define MAXN    16384
#define MAXF    16384
#define MAXG    8192
#define SMP     16
#define MAXQR   (MAXG * SMP)        // 131072 reverse queries
#define MAXP    (MAXQR + MAXG)
#define MAXT    (MAXN + MAXF + MAXQR + MAXG)

// Uniform grid over [-4.75, 4.75]^3; out-of-range points clamp into edge
// cells (conservative for the shell termination bound).
#define GD      48
#define CELLS   (GD * GD * GD)      // 110592
#define LOB     (-4.75f)
#define HCELL   (9.5f / (float)GD)
#define CHUNK   1024
#define NCH     (CELLS / CHUNK)     // 108
#define SENT    3.0e38f

__device__ int    g_cnt[4][CELLS];
__device__ int    g_starts[4][CELLS + 1];
__device__ int    g_cursor[4][CELLS];
__device__ int    g_chtot[4][NCH];
__device__ float4 g_stage[MAXT];      // staged (x,y,z,prob) from k_count
// Paired ref layout: pair p occupies float4[2p] = {x0,x1,y0,y1} and
// float4[2p+1] = {z0,z1,w0,w1}. Cell counts rounded up to even so every
// cell starts on a pair boundary; pad slots hold sentinel (0,0,0,SENT).
__device__ float4 g_pref0[2 * MAXN];  // orig vertices, cell-sorted pairs
__device__ float4 g_pref1[2 * MAXF];  // orig barycenters, cell-sorted pairs
__device__ float4 g_sq0[MAXQR];       // reverse queries, cell-sorted
__device__ float  g_sp0[MAXQR];
__device__ float4 g_sq1[MAXG];        // forward queries
__device__ float  g_sp1[MAXG];
__device__ int    g_pidx[MAXP];       // pending (uncertified) queries
__device__ float  g_pbest[MAXP];
__device__ int    g_npend;
__device__ unsigned g_done;
__device__ double g_fwd, g_rev;
__device__ unsigned g_maxbits;

__device__ __forceinline__ int cellof(float x) {
    int c = (int)floorf((x - LOB) * (1.0f / HCELL));
    return min(max(c, 0), GD - 1);
}

// ---- packed f32x2 helpers (proven in R4) ---------------------------------
__device__ __forceinline__ unsigned long long fma2(unsigned long long a,
                                                   unsigned long long b,
                                                   unsigned long long c) {
    unsigned long long d;
    asm("fma.rn.f32x2 %0, %1, %2, %3;" : "=l"(d) : "l"(a), "l"(b), "l"(c));
    return d;
}
__device__ __forceinline__ unsigned long long dup2(float v) {
    unsigned long long r;
    asm("mov.b64 %0, {%1, %1};" : "=l"(r) : "f"(v));
    return r;
}
__device__ __forceinline__ float2 u2f(unsigned long long v) {
    float2 f;
    asm("mov.b64 {%0, %1}, %2;" : "=f"(f.x), "=f"(f.y) : "l"(v));
    return f;
}

// Deterministic item generator (count pass; fill reads the stage).
__device__ __forceinline__ void item(
    int idx,
    const float* __restrict__ ov, const int* __restrict__ of,
    const float* __restrict__ sv, const int* __restrict__ sf,
    const float* __restrict__ probs,
    const float* __restrict__ r1, const float* __restrict__ r2,
    int N, int F, int G, int S,
    float& x, float& y, float& z, float& prob)
{
    if (idx < N) {
        prob = 0.f;
        x = ov[3*idx]; y = ov[3*idx+1]; z = ov[3*idx+2];
    } else if (idx < N + F) {
        prob = 0.f;
        int f = idx - N;
        int i0 = of[3*f], i1 = of[3*f+1], i2 = of[3*f+2];
        x = (ov[3*i0  ] + ov[3*i1  ] + ov[3*i2  ]) * (1.f/3.f);
        y = (ov[3*i0+1] + ov[3*i1+1] + ov[3*i2+1]) * (1.f/3.f);
        z = (ov[3*i0+2] + ov[3*i1+2] + ov[3*i2+2]) * (1.f/3.f);
    } else if (idx < N + F + G * S) {
        int q = idx - N - F;
        int g = q / S;
        int i0 = sf[3*g], i1 = sf[3*g+1], i2 = sf[3*g+2];
        float sq = sqrtf(r1[q]);
        float rr2 = r2[q];
        float u = 1.f - sq, v = sq * (1.f - rr2), w = sq * rr2;
        x = u*sv[3*i0  ] + v*sv[3*i1  ] + w*sv[3*i2  ];
        y = u*sv[3*i0+1] + v*sv[3*i1+1] + w*sv[3*i2+1];
        z = u*sv[3*i0+2] + v*sv[3*i1+2] + w*sv[3*i2+2];
        prob = probs[g];
    } else {
        int g = idx - N - F - G * S;
        int i0 = sf[3*g], i1 = sf[3*g+1], i2 = sf[3*g+2];
        x = (sv[3*i0  ] + sv[3*i1  ] + sv[3*i2  ]) * (1.f/3.f);
        y = (sv[3*i0+1] + sv[3*i1+1] + sv[3*i2+1]) * (1.f/3.f);
        z = (sv[3*i0+2] + sv[3*i1+2] + sv[3*i2+2]) * (1.f/3.f);
        prob = probs[g];
    }
}

// ---------------------------------------------------------------------------
__global__ void k_zero()
{
    int idx = blockIdx.x * blockDim.x + threadIdx.x;
    if (idx == 0) {
        g_fwd = 0.0; g_rev = 0.0; g_maxbits = 0u; g_npend = 0; g_done = 0u;
    }
    if (idx < 4 * CELLS) ((int*)g_cnt)[idx] = 0;
    // sentinel-init paired ref arrays (odd float4 = {z0,z1,w0,w1})
    if (idx < 2 * MAXN) {
        float4 v = (idx & 1) ? make_float4(0.f, 0.f, SENT, SENT)
                             : make_float4(0.f, 0.f, 0.f, 0.f);
        g_pref0[idx] = v;
        g_pref1[idx] = v;
    }
}

__global__ void k_count(const float* __restrict__ ov, const int* __restrict__ of,
                        const float* __restrict__ sv, const int* __restrict__ sf,
                        const float* __restrict__ probs,
                        const float* __restrict__ r1, const float* __restrict__ r2,
                        int N, int F, int G, int S, int T)
{
    int idx = blockIdx.x * blockDim.x + threadIdx.x;
    if (idx >= T) return;
    float x, y, z, p;
    item(idx, ov, of, sv, sf, probs, r1, r2, N, F, G, S, x, y, z, p);
    g_stage[idx] = make_float4(x, y, z, p);
    const int set = (idx < N) ? 0 : (idx < N + F) ? 1 : (idx < N + F + G*S) ? 2 : 3;
    int cid = (cellof(z) * GD + cellof(y)) * GD + cellof(x);
    atomicAdd(&g_cnt[set][cid], 1);
}

// Per-chunk exclusive scan via shfl (2 barriers). Ref sets (a<2) use counts
// rounded UP TO EVEN so every cell starts on a pair boundary.
__global__ void k_scanA()
{
    const int a = blockIdx.x / NCH, j = blockIdx.x % NCH;
    const int t = threadIdx.x;
    const int wid = t >> 5, lane = t & 31;
    __shared__ int wsum[32];

    int v = g_cnt[a][j * CHUNK + t];
    if (a < 2) v = (v + 1) & ~1;
    int inc = v;
    #pragma unroll
    for (int o = 1; o < 32; o <<= 1) {
        int u = __shfl_up_sync(0xFFFFFFFFu, inc, o);
        if (lane >= o) inc += u;
    }
    if (lane == 31) wsum[wid] = inc;
    __syncthreads();
    if (wid == 0) {
        int w = wsum[lane];
        #pragma unroll
        for (int o = 1; o < 32; o <<= 1) {
            int u = __shfl_up_sync(0xFFFFFFFFu, w, o);
            if (lane >= o) w += u;
        }
        wsum[lane] = w;
    }
    __syncthreads();
    const int inclusive = inc + (wid ? wsum[wid - 1] : 0);
    g_starts[a][j * CHUNK + t] = inclusive - v;
    if (t == CHUNK - 1) g_chtot[a][j] = inclusive;
}

// Each chunk block computes its global offset and applies it.
__global__ void k_scanBC()
{
    const int a = blockIdx.x / NCH, j = blockIdx.x % NCH;
    const int t = threadIdx.x;
    __shared__ int s_off;
    if (t < 32) {
        int acc = 0;
        for (int i = t; i < j; i += 32) acc += g_chtot[a][i];
        #pragma unroll
        for (int o = 16; o > 0; o >>= 1)
            acc += __shfl_xor_sync(0xFFFFFFFFu, acc, o);
        if (t == 0) s_off = acc;
    }
    __syncthreads();
    const int off = s_off;
    const int idx = j * CHUNK + t;
    int s = g_starts[a][idx] + off;
    g_starts[a][idx] = s;
    g_cursor[a][idx] = s;
    if (j == NCH - 1 && t == CHUNK - 1) {
        int cv = g_cnt[a][idx];
        if (a < 2) cv = (cv + 1) & ~1;
        g_starts[a][CELLS] = s + cv;
    }
}

// Fill from staged points. Ref sets scatter into the PAIRED layout.
__global__ void k_fill(int N, int F, int G, int S, int T)
{
    int idx = blockIdx.x * blockDim.x + threadIdx.x;
    if (idx >= T) return;
    float4 st4 = g_stage[idx];
    const float x = st4.x, y = st4.y, z = st4.z, p = st4.w;
    const int set = (idx < N) ? 0 : (idx < N + F) ? 1 : (idx < N + F + G*S) ? 2 : 3;
    int cid = (cellof(z) * GD + cellof(y)) * GD + cellof(x);
    int pos = atomicAdd(&g_cursor[set][cid], 1);
    const float ww = x*x + y*y + z*z;
    if (set < 2) {
        float* b = (float*)&(set == 0 ? g_pref0 : g_pref1)[2 * (pos >> 1)];
        const int o = pos & 1;
        b[0+o] = x; b[2+o] = y; b[4+o] = z; b[6+o] = ww;
    } else if (set == 2) {
        g_sq0[pos] = make_float4(x, y, z, ww); g_sp0[pos] = p;
    } else {
        g_sq1[pos] = make_float4(x, y, z, ww); g_sp1[pos] = p;
    }
}

// Packed scan of one row range [s,e) (even bounds). Updates best0/best1.
__device__ __forceinline__ void scan_row_f32x2(
    const ulonglong2* __restrict__ pr, int s, int e,
    unsigned long long a2, unsigned long long b2, unsigned long long c2,
    float& best0, float& best1)
{
    for (int pp = (s >> 1); pp < (e >> 1); pp++) {
        const ulonglong2 P = pr[2*pp];       // (x0x1, y0y1)
        const ulonglong2 Z = pr[2*pp+1];     // (z0z1, w0w1)
        unsigned long long t = fma2(c2, Z.x, Z.y);
        t = fma2(b2, P.y, t);
        t = fma2(a2, P.x, t);
        const float2 sres = u2f(t);
        best0 = fminf(best0, sres.x);
        best1 = fminf(best1, sres.y);
    }
}

// ---------------------------------------------------------------------------
// Phase 1: thread-per-query flat 3x3x3 over CELL-SORTED queries (coherence
// load-bearing). Candidate loop is packed f32x2 (2 refs / 3 FFMA2).
// Certify d <= h (sound). Uncertified -> pending list with seeded best.
// ---------------------------------------------------------------------------
#define QT 256
__global__ void __launch_bounds__(QT)
k_query1(int brev, int nq_rev, int nq_fwd)
{
    const bool rev = (blockIdx.x < (unsigned)brev);
    const ulonglong2* __restrict__ pr =
        (const ulonglong2*)(rev ? g_pref0 : g_pref1);
    const int*    __restrict__ st   = rev ? g_starts[0] : g_starts[1];
    const float4* __restrict__ qarr = rev ? g_sq0       : g_sq1;
    const float*  __restrict__ parr = rev ? g_sp0       : g_sp1;
    const int nq = rev ? nq_rev : nq_fwd;
    const int qi = (rev ? blockIdx.x : blockIdx.x - brev) * QT + threadIdx.x;

    float contrib = 0.f, dmax = 0.f;

    if (qi < nq) {
        const float4 Q = qarr[qi];
        const float qq = Q.w;
        const unsigned long long a2 = dup2(-2.f * Q.x);
        const unsigned long long b2 = dup2(-2.f * Q.y);
        const unsigned long long c2 = dup2(-2.f * Q.z);
        const int cx = cellof(Q.x), cy = cellof(Q.y), cz = cellof(Q.z);
        const int xlo = max(cx - 1, 0), xhi = min(cx + 1, GD - 1);
        const int xn  = xhi - xlo + 1;

        int s[9], e[9];
        #pragma unroll
        for (int dz = 0; dz < 3; dz++) {
            #pragma unroll
            for (int dy = 0; dy < 3; dy++) {
                const int z = cz + dz - 1, y = cy + dy - 1;
                const int k = dz * 3 + dy;
                if (z < 0 || z >= GD || y < 0 || y >= GD) { s[k] = 0; e[k] = 0; }
                else {
                    const int c0 = (z * GD + y) * GD + xlo;
                    s[k] = st[c0]; e[k] = st[c0 + xn];
                }
            }
        }

        float best0 = SENT, best1 = SENT;
        #pragma unroll
        for (int k = 0; k < 9; k++)
            scan_row_f32x2(pr, s[k], e[k], a2, b2, c2, best0, best1);
        float best = fminf(best0, best1);

        const float d2 = fmaxf(best + qq, 0.f);
        if (d2 <= HCELL * HCELL) {
            const float d = sqrtf(fmaxf(d2, 1e-12f));
            const float p = parr[qi];
            contrib = rev ? p * d : fmaf(p, d, 1e-4f * (1.f - p));
            if (rev) dmax = d;
        } else {
            int pos = atomicAdd(&g_npend, 1);
            g_pidx[pos]  = rev ? qi : (qi | 0x40000000);
            g_pbest[pos] = best;
        }
    }

    float sv2 = contrib, mv = dmax;
    #pragma unroll
    for (int o = 16; o > 0; o >>= 1) {
        sv2 += __shfl_xor_sync(0xFFFFFFFFu, sv2, o);
        mv = fmaxf(mv, __shfl_xor_sync(0xFFFFFFFFu, mv, o));
    }
    __shared__ float rs[QT / 32], rm[QT / 32];
    const int warp = threadIdx.x >> 5, lane = threadIdx.x & 31;
    if (lane == 0) { rs[warp] = sv2; rm[warp] = mv; }
    __syncthreads();
    if (threadIdx.x == 0) {
        float s2 = 0.f, m2 = 0.f;
        #pragma unroll
        for (int i = 0; i < QT / 32; i++) { s2 += rs[i]; m2 = fmaxf(m2, rm[i]); }
        atomicAdd(rev ? &g_rev : &g_fwd, (double)s2);
        if (rev) atomicMax(&g_maxbits, __float_as_uint(m2));
    }
}

// ---------------------------------------------------------------------------
// Phase 2: warp-per-pending-query shell walk from r=2 (seeded best), packed
// candidate loop. Last block (atomic ticket) writes the final scalar.
// ---------------------------------------------------------------------------
#define QT2   256
#define NB2   592
__global__ void __launch_bounds__(QT2)
k_query2(float* __restrict__ out)
{
    const int lane = threadIdx.x & 31;
    const int wid  = threadIdx.x >> 5;
    const int gw   = blockIdx.x * (QT2 / 32) + wid;
    const int nw   = NB2 * (QT2 / 32);
    const int npend = g_npend;

    float rsum = 0.f, fsum = 0.f, rmax = 0.f;

    for (int w = gw; w < npend; w += nw) {
        const int code = g_pidx[w];
        const bool rev = !(code & 0x40000000);
        const int qi = code & 0x3FFFFFFF;
        const ulonglong2* __restrict__ pr =
            (const ulonglong2*)(rev ? g_pref0 : g_pref1);
        const int* __restrict__ st = rev ? g_starts[0] : g_starts[1];
        const float4 Q = rev ? g_sq0[qi] : g_sq1[qi];
        const float qq = Q.w;
        const unsigned long long a2 = dup2(-2.f * Q.x);
        const unsigned long long b2 = dup2(-2.f * Q.y);
        const unsigned long long c2 = dup2(-2.f * Q.z);
        const int cx = cellof(Q.x), cy = cellof(Q.y), cz = cellof(Q.z);

        float best = g_pbest[w];

        for (int r = 2; r < GD; r++) {
            const int xlo = max(cx - r, 0), xhi = min(cx + r, GD - 1);
            const int ylo = max(cy - r, 0), yhi = min(cy + r, GD - 1);
            const int zlo = max(cz - r, 0), zhi = min(cz + r, GD - 1);
            const unsigned ny   = (unsigned)(yhi - ylo + 1);
            const int      xn   = xhi - xlo + 1;

            int capcnt = 0, capz0 = 0, capz1 = 0;
            if (cz - r >= 0)      { capz0 = cz - r; capcnt = 1; }
            if (cz + r <= GD - 1) { if (capcnt == 0) capz0 = cz + r; else capz1 = cz + r; capcnt++; }
            const int izlo = max(cz - r + 1, 0), izhi = min(cz + r - 1, GD - 1);
            const unsigned nzint = (unsigned)max(izhi - izlo + 1, 0);
            int nys = 0, ys0 = 0, ys1 = 0;
            if (cy - r >= 0)      { ys0 = cy - r; nys = 1; }
            if (cy + r <= GD - 1) { if (nys == 0) ys0 = cy + r; else ys1 = cy + r; nys++; }
            const int iylo = max(cy - r + 1, 0), iyhi = min(cy + r - 1, GD - 1);
            const unsigned nyint = (unsigned)max(iyhi - iylo + 1, 0);
            int nxs = 0, xs0 = 0, xs1 = 0;
            if (cx - r >= 0)      { xs0 = cx - r; nxs = 1; }
            if (cx + r <= GD - 1) { if (nxs == 0) xs0 = cx + r; else xs1 = cx + r; nxs++; }

            const unsigned nA = (unsigned)capcnt * ny;
            const unsigned nB = (unsigned)nys * nzint;
            const unsigned nzy = nzint * nyint;
            const unsigned nC = (unsigned)nxs * nzy;
            const unsigned tot = nA + nB + nC;

            float best0 = best, best1 = SENT;
            for (unsigned t = (unsigned)lane; t < tot; t += 32) {
                int c0, len;
                if (t < nA) {
                    unsigned ci = t / ny, yr = t - ci * ny;
                    int z = ci ? capz1 : capz0;
                    c0 = (z * GD + (ylo + (int)yr)) * GD + xlo; len = xn;
                } else if (t < nA + nB) {
                    unsigned t2 = t - nA;
                    unsigned si = t2 / nzint, zi = t2 - si * nzint;
                    int y = si ? ys1 : ys0;
                    c0 = (((int)zi + izlo) * GD + y) * GD + xlo; len = xn;
                } else {
                    unsigned t3 = t - nA - nB;
                    unsigned xi = t3 / nzy, rem = t3 - xi * nzy;
                    unsigned zi = rem / nyint, yi = rem - zi * nyint;
                    int x = xi ? xs1 : xs0;
                    c0 = (((int)zi + izlo) * GD + ((int)yi + iylo)) * GD + x; len = 1;
                }
                scan_row_f32x2(pr, st[c0], st[c0 + len], a2, b2, c2, best0, best1);
            }
            best = fminf(best0, best1);

            #pragma unroll
            for (int o = 16; o > 0; o >>= 1)
                best = fminf(best, __shfl_xor_sync(0xFFFFFFFFu, best, o));

            const float d2 = fmaxf(best + qq, 0.f);
            const float cov = (float)r * HCELL;
            if (d2 <= cov * cov) break;
            if (xlo == 0 && ylo == 0 && zlo == 0 &&
                xhi == GD - 1 && yhi == GD - 1 && zhi == GD - 1) break;
        }

        if (lane == 0) {
            const float d = sqrtf(fmaxf(best + qq, 1e-12f));
            const float p = rev ? g_sp0[qi] : g_sp1[qi];
            if (rev) { rsum += p * d; rmax = fmaxf(rmax, d); }
            else     { fsum += fmaf(p, d, 1e-4f * (1.f - p)); }
        }
    }

    __shared__ float shr[QT2 / 32], shf[QT2 / 32], shm[QT2 / 32];
    if (lane == 0) { shr[wid] = rsum; shf[wid] = fsum; shm[wid] = rmax; }
    __syncthreads();
    if (threadIdx.x == 0) {
        float r2s = 0.f, f2s = 0.f, m2 = 0.f;
        #pragma unroll
        for (int i = 0; i < QT2 / 32; i++) {
            r2s += shr[i]; f2s += shf[i]; m2 = fmaxf(m2, shm[i]);
        }
        if (r2s != 0.f) atomicAdd(&g_rev, (double)r2s);
        if (f2s != 0.f) atomicAdd(&g_fwd, (double)f2s);
        atomicMax(&g_maxbits, __float_as_uint(m2));

        __threadfence();
        unsigned ticket = atomicAdd(&g_done, 1u);
        if (ticket == (unsigned)(NB2 - 1)) {
            float maxd = __uint_as_float(g_maxbits) + 1e-8f;
            double result = g_fwd + g_rev * (0.1 / (double)maxd);
            out[0] = (float)result;
        }
    }
}

// ---------------------------------------------------------------------------
extern "C" void kernel_launch(void* const* d_in, const int* in_sizes, int n_in,
                              void* d_out, int out_size)
{
    const float* ov    = (const float*)d_in[0];
    const int*   of    = (const int*)  d_in[1];
    const float* sv    = (const float*)d_in[2];
    const int*   sf    = (const int*)  d_in[3];
    const float* probs = (const float*)d_in[4];
    const float* r1    = (const float*)d_in[5];
    const float* r2    = (const float*)d_in[6];

    const int N = in_sizes[0] / 3;     // 16384
    const int F = in_sizes[1] / 3;     // 16384
    const int G = in_sizes[3] / 3;     // 8192
    const int S = in_sizes[5] / G;     // 16

    const int nq_rev = G * S;          // 131072
    const int nq_fwd = G;              // 8192
    const int T = N + F + nq_rev + nq_fwd;

    k_zero  <<<(4 * CELLS + 255) / 256, 256>>>();
    k_count <<<(T + 255) / 256, 256>>>(ov, of, sv, sf, probs, r1, r2, N, F, G, S, T);
    k_scanA <<<4 * NCH, CHUNK>>>();
    k_scanBC<<<4 * NCH, CHUNK>>>();
    k_fill  <<<(T + 255) / 256, 256>>>(N, F, G, S, T);

    const int brev = (nq_rev + QT - 1) / QT;   // 512
    const int bfwd = (nq_fwd + QT - 1) / QT;   // 32
    k_query1<<<brev + bfwd, QT>>>(brev, nq_rev, nq_fwd);
    k_query2<<<NB2, QT2>>>((float*)d_out);
}

// round 16
// speedup vs baseline: 1.0278x; 1.0274x over previous
#include <cuda_runtime.h>
#include <cuda_bf16.h>
#include <math.h>

// Problem shapes (fixed dataset): N=F=16384, G=8192, S=16
#define MAXN    16384
#define MAXF    16384
#define MAXG    8192
#define SMP     16
#define MAXQR   (MAXG * SMP)        // 131072 reverse queries
#define MAXP    (MAXQR + MAXG)
#define MAXT    (MAXN + MAXF + MAXQR + MAXG)

// Uniform grid over [-4.75, 4.75]^3; out-of-range points clamp into edge
// cells (conservative for the shell termination bound).
#define GD      48
#define CELLS   (GD * GD * GD)      // 110592
#define LOB     (-4.75f)
#define HCELL   (9.5f / (float)GD)
#define HHALF   (0.5f * HCELL)
#define CHUNK   1024
#define NCH     (CELLS / CHUNK)     // 108

__device__ int    g_cnt[4][CELLS];
__device__ int    g_starts[4][CELLS + 1];
__device__ int    g_cursor[4][CELLS];
__device__ int    g_chtot[4][NCH];
__device__ float4 g_stage[MAXT];    // staged (x,y,z,prob) from k_count
__device__ float4 g_sref0[MAXN];    // orig vertices  (x,y,z,|p|^2), cell-sorted
__device__ float4 g_sref1[MAXF];    // orig barycenters
__device__ float4 g_sq0[MAXQR];     // reverse queries, cell-sorted
__device__ float  g_sp0[MAXQR];
__device__ float4 g_sq1[MAXG];      // forward queries
__device__ float  g_sp1[MAXG];
__device__ int    g_pidx[MAXP];     // pending (uncertified) queries
__device__ float  g_pbest[MAXP];
__device__ int    g_npend;
__device__ unsigned g_done;
__device__ double g_fwd, g_rev;
__device__ unsigned g_maxbits;

__device__ __forceinline__ int cellof(float x) {
    int c = (int)floorf((x - LOB) * (1.0f / HCELL));
    return min(max(c, 0), GD - 1);
}

// Deterministic item generator (count pass only; fill reads the stage).
__device__ __forceinline__ void item(
    int idx,
    const float* __restrict__ ov, const int* __restrict__ of,
    const float* __restrict__ sv, const int* __restrict__ sf,
    const float* __restrict__ probs,
    const float* __restrict__ r1, const float* __restrict__ r2,
    int N, int F, int G, int S,
    float& x, float& y, float& z, float& prob)
{
    if (idx < N) {
        prob = 0.f;
        x = ov[3*idx]; y = ov[3*idx+1]; z = ov[3*idx+2];
    } else if (idx < N + F) {
        prob = 0.f;
        int f = idx - N;
        int i0 = of[3*f], i1 = of[3*f+1], i2 = of[3*f+2];
        x = (ov[3*i0  ] + ov[3*i1  ] + ov[3*i2  ]) * (1.f/3.f);
        y = (ov[3*i0+1] + ov[3*i1+1] + ov[3*i2+1]) * (1.f/3.f);
        z = (ov[3*i0+2] + ov[3*i1+2] + ov[3*i2+2]) * (1.f/3.f);
    } else if (idx < N + F + G * S) {
        int q = idx - N - F;
        int g = q / S;
        int i0 = sf[3*g], i1 = sf[3*g+1], i2 = sf[3*g+2];
        float sq = sqrtf(r1[q]);
        float rr2 = r2[q];
        float u = 1.f - sq, v = sq * (1.f - rr2), w = sq * rr2;
        x = u*sv[3*i0  ] + v*sv[3*i1  ] + w*sv[3*i2  ];
        y = u*sv[3*i0+1] + v*sv[3*i1+1] + w*sv[3*i2+1];
        z = u*sv[3*i0+2] + v*sv[3*i1+2] + w*sv[3*i2+2];
        prob = probs[g];
    } else {
        int g = idx - N - F - G * S;
        int i0 = sf[3*g], i1 = sf[3*g+1], i2 = sf[3*g+2];
        x = (sv[3*i0  ] + sv[3*i1  ] + sv[3*i2  ]) * (1.f/3.f);
        y = (sv[3*i0+1] + sv[3*i1+1] + sv[3*i2+1]) * (1.f/3.f);
        z = (sv[3*i0+2] + sv[3*i1+2] + sv[3*i2+2]) * (1.f/3.f);
        prob = probs[g];
    }
}

// ---------------------------------------------------------------------------
__global__ void k_zero()
{
    int idx = blockIdx.x * blockDim.x + threadIdx.x;
    if (idx == 0) {
        g_fwd = 0.0; g_rev = 0.0; g_maxbits = 0u; g_npend = 0; g_done = 0u;
    }
    if (idx < 4 * CELLS) ((int*)g_cnt)[idx] = 0;
}

__global__ void k_count(const float* __restrict__ ov, const int* __restrict__ of,
                        const float* __restrict__ sv, const int* __restrict__ sf,
                        const float* __restrict__ probs,
                        const float* __restrict__ r1, const float* __restrict__ r2,
                        int N, int F, int G, int S, int T)
{
    int idx = blockIdx.x * blockDim.x + threadIdx.x;
    if (idx >= T) return;
    float x, y, z, p;
    item(idx, ov, of, sv, sf, probs, r1, r2, N, F, G, S, x, y, z, p);
    g_stage[idx] = make_float4(x, y, z, p);
    const int set = (idx < N) ? 0 : (idx < N + F) ? 1 : (idx < N + F + G*S) ? 2 : 3;
    int cid = (cellof(z) * GD + cellof(y)) * GD + cellof(x);
    atomicAdd(&g_cnt[set][cid], 1);
}

// Per-chunk exclusive scan via shfl (2 barriers), chunk totals out.
__global__ void k_scanA()
{
    const int a = blockIdx.x / NCH, j = blockIdx.x % NCH;
    const int t = threadIdx.x;
    const int wid = t >> 5, lane = t & 31;
    __shared__ int wsum[32];

    int v = g_cnt[a][j * CHUNK + t];
    int inc = v;
    #pragma unroll
    for (int o = 1; o < 32; o <<= 1) {
        int u = __shfl_up_sync(0xFFFFFFFFu, inc, o);
        if (lane >= o) inc += u;
    }
    if (lane == 31) wsum[wid] = inc;
    __syncthreads();
    if (wid == 0) {
        int w = wsum[lane];
        #pragma unroll
        for (int o = 1; o < 32; o <<= 1) {
            int u = __shfl_up_sync(0xFFFFFFFFu, w, o);
            if (lane >= o) w += u;
        }
        wsum[lane] = w;
    }
    __syncthreads();
    const int inclusive = inc + (wid ? wsum[wid - 1] : 0);
    g_starts[a][j * CHUNK + t] = inclusive - v;
    if (t == CHUNK - 1) g_chtot[a][j] = inclusive;
}

// Each chunk block computes its global offset (warp-reduce over preceding
// chunk totals) and applies it; writes starts + cursor + sentinel.
__global__ void k_scanBC()
{
    const int a = blockIdx.x / NCH, j = blockIdx.x % NCH;
    const int t = threadIdx.x;
    __shared__ int s_off;
    if (t < 32) {
        int acc = 0;
        for (int i = t; i < j; i += 32) acc += g_chtot[a][i];
        #pragma unroll
        for (int o = 16; o > 0; o >>= 1)
            acc += __shfl_xor_sync(0xFFFFFFFFu, acc, o);
        if (t == 0) s_off = acc;
    }
    __syncthreads();
    const int off = s_off;
    const int idx = j * CHUNK + t;
    int s = g_starts[a][idx] + off;
    g_starts[a][idx] = s;
    g_cursor[a][idx] = s;
    if (j == NCH - 1 && t == CHUNK - 1)
        g_starts[a][CELLS] = s + g_cnt[a][idx];
}

// Fill from the staged points (coalesced read; no regathering).
__global__ void k_fill(int N, int F, int G, int S, int T)
{
    int idx = blockIdx.x * blockDim.x + threadIdx.x;
    if (idx >= T) return;
    float4 st4 = g_stage[idx];
    const float x = st4.x, y = st4.y, z = st4.z, p = st4.w;
    const int set = (idx < N) ? 0 : (idx < N + F) ? 1 : (idx < N + F + G*S) ? 2 : 3;
    int cid = (cellof(z) * GD + cellof(y)) * GD + cellof(x);
    int pos = atomicAdd(&g_cursor[set][cid], 1);
    float4 v4 = make_float4(x, y, z, x*x + y*y + z*z);
    if      (set == 0) g_sref0[pos] = v4;
    else if (set == 1) g_sref1[pos] = v4;
    else if (set == 2) { g_sq0[pos] = v4; g_sp0[pos] = p; }
    else               { g_sq1[pos] = v4; g_sp1[pos] = p; }
}

// ---------------------------------------------------------------------------
// Phase 1: thread-per-query OCTANT 2x2x2 box over CELL-SORTED queries.
// Octant choice per axis (fx >= h/2 ? +1 : -1) guarantees the ball of
// radius h/2 around q lies inside the box (clamping only extends coverage),
// so certify d <= h/2. ~35 candidates vs ~119 for the 3^3 box; ~10% pend.
// ---------------------------------------------------------------------------
#define QT 256
__global__ void __launch_bounds__(QT)
k_query1(int brev, int nq_rev, int nq_fwd)
{
    const bool rev = (blockIdx.x < (unsigned)brev);
    const float4* __restrict__ refs = rev ? g_sref0     : g_sref1;
    const int*    __restrict__ st   = rev ? g_starts[0] : g_starts[1];
    const float4* __restrict__ qarr = rev ? g_sq0       : g_sq1;
    const float*  __restrict__ parr = rev ? g_sp0       : g_sp1;
    const int nq = rev ? nq_rev : nq_fwd;
    const int qi = (rev ? blockIdx.x : blockIdx.x - brev) * QT + threadIdx.x;

    float contrib = 0.f, dmax = 0.f;

    if (qi < nq) {
        const float4 Q = qarr[qi];
        const float a = -2.f * Q.x, b = -2.f * Q.y, c = -2.f * Q.z;
        const float qq = Q.w;
        const int cx = cellof(Q.x), cy = cellof(Q.y), cz = cellof(Q.z);

        // octant selection per axis
        const float fx = Q.x - (LOB + cx * HCELL);
        const float fy = Q.y - (LOB + cy * HCELL);
        const float fz = Q.z - (LOB + cz * HCELL);
        const int ox = (fx >= HHALF) ? 1 : -1;
        const int oy = (fy >= HHALF) ? 1 : -1;
        const int oz = (fz >= HHALF) ? 1 : -1;
        const int xlo = max(0, min(cx, cx + ox));
        const int xhi = min(GD - 1, max(cx, cx + ox));
        const int xn  = xhi - xlo + 1;
        const int ylo = max(0, min(cy, cy + oy));
        const int yhi = min(GD - 1, max(cy, cy + oy));
        const int zlo = max(0, min(cz, cz + oz));
        const int zhi = min(GD - 1, max(cz, cz + oz));

        // up to 4 x-contiguous rows; duplicates when clamped (idempotent min)
        int s[4], e[4];
        #pragma unroll
        for (int k = 0; k < 4; k++) {
            const int z = (k & 2) ? zhi : zlo;
            const int y = (k & 1) ? yhi : ylo;
            const int c0 = (z * GD + y) * GD + xlo;
            s[k] = st[c0]; e[k] = st[c0 + xn];
        }

        float best = 3.4e38f;    // min(|p|^2 - 2 q.p);  d^2 = best + qq
        #pragma unroll
        for (int k = 0; k < 4; k++) {
            for (int i = s[k]; i < e[k]; i++) {
                float4 w = refs[i];
                best = fminf(best, fmaf(a, w.x, fmaf(b, w.y, fmaf(c, w.z, w.w))));
            }
        }

        const float d2 = fmaxf(best + qq, 0.f);
        if (d2 <= HHALF * HHALF) {
            const float d = sqrtf(fmaxf(d2, 1e-12f));
            const float p = parr[qi];
            contrib = rev ? p * d : fmaf(p, d, 1e-4f * (1.f - p));
            if (rev) dmax = d;
        } else {
            int pos = atomicAdd(&g_npend, 1);
            g_pidx[pos]  = rev ? qi : (qi | 0x40000000);
            g_pbest[pos] = best;
        }
    }

    float sv2 = contrib, mv = dmax;
    #pragma unroll
    for (int o = 16; o > 0; o >>= 1) {
        sv2 += __shfl_xor_sync(0xFFFFFFFFu, sv2, o);
        mv = fmaxf(mv, __shfl_xor_sync(0xFFFFFFFFu, mv, o));
    }
    __shared__ float rs[QT / 32], rm[QT / 32];
    const int warp = threadIdx.x >> 5, lane = threadIdx.x & 31;
    if (lane == 0) { rs[warp] = sv2; rm[warp] = mv; }
    __syncthreads();
    if (threadIdx.x == 0) {
        float s2 = 0.f, m2 = 0.f;
        #pragma unroll
        for (int i = 0; i < QT / 32; i++) { s2 += rs[i]; m2 = fmaxf(m2, rm[i]); }
        atomicAdd(rev ? &g_rev : &g_fwd, (double)s2);
        if (rev) atomicMax(&g_maxbits, __float_as_uint(m2));
    }
}

// ---------------------------------------------------------------------------
// Phase 2: warp-per-pending-query shell walk from r=1 (octant box is inside
// the r<=1 region; rescans are idempotent under min), seeded best.
// Last block to finish (atomic ticket) writes the final scalar.
// ---------------------------------------------------------------------------
#define QT2   256
#define NB2   592
__global__ void __launch_bounds__(QT2)
k_query2(float* __restrict__ out)
{
    const int lane = threadIdx.x & 31;
    const int wid  = threadIdx.x >> 5;
    const int gw   = blockIdx.x * (QT2 / 32) + wid;
    const int nw   = NB2 * (QT2 / 32);
    const int npend = g_npend;

    float rsum = 0.f, fsum = 0.f, rmax = 0.f;

    for (int w = gw; w < npend; w += nw) {
        const int code = g_pidx[w];
        const bool rev = !(code & 0x40000000);
        const int qi = code & 0x3FFFFFFF;
        const float4* __restrict__ refs = rev ? g_sref0     : g_sref1;
        const int*    __restrict__ st   = rev ? g_starts[0] : g_starts[1];
        const float4 Q = rev ? g_sq0[qi] : g_sq1[qi];
        const float a = -2.f * Q.x, b = -2.f * Q.y, c = -2.f * Q.z;
        const float qq = Q.w;
        const int cx = cellof(Q.x), cy = cellof(Q.y), cz = cellof(Q.z);

        float best = g_pbest[w];

        for (int r = 1; r < GD; r++) {
            const int xlo = max(cx - r, 0), xhi = min(cx + r, GD - 1);
            const int ylo = max(cy - r, 0), yhi = min(cy + r, GD - 1);
            const int zlo = max(cz - r, 0), zhi = min(cz + r, GD - 1);
            const unsigned ny   = (unsigned)(yhi - ylo + 1);
            const int      xlen = xhi - xlo + 1;

            int capcnt = 0, capz0 = 0, capz1 = 0;
            if (cz - r >= 0)      { capz0 = cz - r; capcnt = 1; }
            if (cz + r <= GD - 1) { if (capcnt == 0) capz0 = cz + r; else capz1 = cz + r; capcnt++; }
            const int izlo = max(cz - r + 1, 0), izhi = min(cz + r - 1, GD - 1);
            const unsigned nzint = (unsigned)max(izhi - izlo + 1, 0);
            int nys = 0, ys0 = 0, ys1 = 0;
            if (cy - r >= 0)      { ys0 = cy - r; nys = 1; }
            if (cy + r <= GD - 1) { if (nys == 0) ys0 = cy + r; else ys1 = cy + r; nys++; }
            const int iylo = max(cy - r + 1, 0), iyhi = min(cy + r - 1, GD - 1);
            const unsigned nyint = (unsigned)max(iyhi - iylo + 1, 0);
            int nxs = 0, xs0 = 0, xs1 = 0;
            if (cx - r >= 0)      { xs0 = cx - r; nxs = 1; }
            if (cx + r <= GD - 1) { if (nxs == 0) xs0 = cx + r; else xs1 = cx + r; nxs++; }

            const unsigned nA = (unsigned)capcnt * ny;
            const unsigned nB = (unsigned)nys * nzint;
            const unsigned nzy = nzint * nyint;
            const unsigned nC = (unsigned)nxs * nzy;
            const unsigned tot = nA + nB + nC;

            for (unsigned t = (unsigned)lane; t < tot; t += 32) {
                int c0, len;
                if (t < nA) {
                    unsigned ci = t / ny, yr = t - ci * ny;
                    int z = ci ? capz1 : capz0;
                    c0 = (z * GD + (ylo + (int)yr)) * GD + xlo; len = xlen;
                } else if (t < nA + nB) {
                    unsigned t2 = t - nA;
                    unsigned si = t2 / nzint, zi = t2 - si * nzint;
                    int y = si ? ys1 : ys0;
                    c0 = (((int)zi + izlo) * GD + y) * GD + xlo; len = xlen;
                } else {
                    unsigned t3 = t - nA - nB;
                    unsigned xi = t3 / nzy, rem = t3 - xi * nzy;
                    unsigned zi = rem / nyint, yi = rem - zi * nyint;
                    int x = xi ? xs1 : xs0;
                    c0 = (((int)zi + izlo) * GD + ((int)yi + iylo)) * GD + x; len = 1;
                }
                const int s = st[c0], e = st[c0 + len];
                for (int i = s; i < e; i++) {
                    float4 wv = refs[i];
                    best = fminf(best, fmaf(a, wv.x, fmaf(b, wv.y, fmaf(c, wv.z, wv.w))));
                }
            }

            #pragma unroll
            for (int o = 16; o > 0; o >>= 1)
                best = fminf(best, __shfl_xor_sync(0xFFFFFFFFu, best, o));

            const float d2 = fmaxf(best + qq, 0.f);
            const float cov = (float)r * HCELL;
            if (d2 <= cov * cov) break;
            if (xlo == 0 && ylo == 0 && zlo == 0 &&
                xhi == GD - 1 && yhi == GD - 1 && zhi == GD - 1) break;
        }

        if (lane == 0) {
            const float d = sqrtf(fmaxf(best + qq, 1e-12f));
            const float p = rev ? g_sp0[qi] : g_sp1[qi];
            if (rev) { rsum += p * d; rmax = fmaxf(rmax, d); }
            else     { fsum += fmaf(p, d, 1e-4f * (1.f - p)); }
        }
    }

    __shared__ float shr[QT2 / 32], shf[QT2 / 32], shm[QT2 / 32];
    if (lane == 0) { shr[wid] = rsum; shf[wid] = fsum; shm[wid] = rmax; }
    __syncthreads();
    if (threadIdx.x == 0) {
        float r2s = 0.f, f2s = 0.f, m2 = 0.f;
        #pragma unroll
        for (int i = 0; i < QT2 / 32; i++) {
            r2s += shr[i]; f2s += shf[i]; m2 = fmaxf(m2, shm[i]);
        }
        if (r2s != 0.f) atomicAdd(&g_rev, (double)r2s);
        if (f2s != 0.f) atomicAdd(&g_fwd, (double)f2s);
        atomicMax(&g_maxbits, __float_as_uint(m2));

        __threadfence();
        unsigned ticket = atomicAdd(&g_done, 1u);
        if (ticket == (unsigned)(NB2 - 1)) {
            float maxd = __uint_as_float(g_maxbits) + 1e-8f;
            double result = g_fwd + g_rev * (0.1 / (double)maxd);
            out[0] = (float)result;
        }
    }
}

// ---------------------------------------------------------------------------
extern "C" void kernel_launch(void* const* d_in, const int* in_sizes, int n_in,
                              void* d_out, int out_size)
{
    const float* ov    = (const float*)d_in[0];
    const int*   of    = (const int*)  d_in[1];
    const float* sv    = (const float*)d_in[2];
    const int*   sf    = (const int*)  d_in[3];
    const float* probs = (const float*)d_in[4];
    const float* r1    = (const float*)d_in[5];
    const float* r2    = (const float*)d_in[6];

    const int N = in_sizes[0] / 3;     // 16384
    const int F = in_sizes[1] / 3;     // 16384
    const int G = in_sizes[3] / 3;     // 8192
    const int S = in_sizes[5] / G;     // 16

    const int nq_rev = G * S;          // 131072
    const int nq_fwd = G;              // 8192
    const int T = N + F + nq_rev + nq_fwd;

    k_zero  <<<(4 * CELLS + 255) / 256, 256>>>();
    k_count <<<(T + 255) / 256, 256>>>(ov, of, sv, sf, probs, r1, r2, N, F, G, S, T);
    k_scanA <<<4 * NCH, CHUNK>>>();
    k_scanBC<<<4 * NCH, CHUNK>>>();
    k_fill  <<<(T + 255) / 256, 256>>>(N, F, G, S, T);

    const int brev = (nq_rev + QT - 1) / QT;   // 512
    const int bfwd = (nq_fwd + QT - 1) / QT;   // 32
    k_query1<<<brev + bfwd, QT>>>(brev, nq_rev, nq_fwd);
    k_query2<<<NB2, QT2>>>((float*)d_out);
}